// round 1
// baseline (speedup 1.0000x reference)
#include <cuda_runtime.h>
#include <cuda_bf16.h>

// Problem constants
#define TRAJ      25      // trajectories per outer
#define NT        10      // mid-segment time samples (EVAL_POINTS//3)
#define NS        10      // line-of-sight samples (NUM_LOS)
#define GDIM      200     // voxel grid per axis
#define MAP_ELEMS 8000000 // 200^3
#define VFOV_C    0.3490658503988659f   // deg2rad(20)

// Inputs (metadata order): Df [B,3,3], Dp [B,3,3], goal [B,3], L [6,6],
// sdf_maps [M,200,200,200], min_bounds [M,3], map_id [OUTER] int32
// Output: float32 [B], B = OUTER*25

__global__ __launch_bounds__(256) void track_loss_kernel(
    const float* __restrict__ Df, const float* __restrict__ Dp,
    const float* __restrict__ goal, const float* __restrict__ L,
    const float* __restrict__ sdf, const float* __restrict__ minb,
    const int*   __restrict__ map_id, float* __restrict__ out)
{
    const int o   = blockIdx.x;
    const int tid = threadIdx.x;

    __shared__ float sL[36];
    __shared__ float sOcc[256];
    __shared__ float sPen[256];
    __shared__ float sG[3];
    __shared__ float sMb[3];
    __shared__ int   sMap;

    if (tid < 36) sL[tid] = L[tid];
    if (tid == 0) {
        int m = map_id[o];
        sMap  = m;
        sMb[0] = minb[m * 3 + 0];
        sMb[1] = minb[m * 3 + 1];
        sMb[2] = minb[m * 3 + 2];
        // goal_o = goal of the first trajectory in this outer group
        sG[0] = goal[(long long)o * TRAJ * 3 + 0];
        sG[1] = goal[(long long)o * TRAJ * 3 + 1];
        sG[2] = goal[(long long)o * TRAJ * 3 + 2];
    }
    __syncthreads();

    float occ_val = 0.0f, pen_val = 0.0f;

    if (tid < TRAJ * NT) {
        const int j  = tid / NT;        // trajectory within outer
        const int it = tid - j * NT;    // time sample index
        const int b  = o * TRAJ + j;

        // --- quintic coefficients: coe[c][i] = sum_j L[i][j] * d[c][j] ---
        float coe[3][6];
        #pragma unroll
        for (int c = 0; c < 3; c++) {
            const float d0 = Df[b * 9 + c * 3 + 0];
            const float d1 = Df[b * 9 + c * 3 + 1];
            const float d2 = Df[b * 9 + c * 3 + 2];
            const float d3 = Dp[b * 9 + c * 3 + 0];
            const float d4 = Dp[b * 9 + c * 3 + 1];
            const float d5 = Dp[b * 9 + c * 3 + 2];
            #pragma unroll
            for (int i = 0; i < 6; i++) {
                coe[c][i] = sL[i * 6 + 0] * d0 + sL[i * 6 + 1] * d1
                          + sL[i * 6 + 2] * d2 + sL[i * 6 + 3] * d3
                          + sL[i * 6 + 4] * d4 + sL[i * 6 + 5] * d5;
            }
        }

        // t = linspace(0.66, 1.32, 10)[it]
        const float t = 0.66f + (float)it * ((1.32f - 0.66f) / 9.0f);

        // position (quintic) and velocity (derivative quartic), Horner form
        float pos[3], vel[3];
        #pragma unroll
        for (int c = 0; c < 3; c++) {
            float p = coe[c][5];
            p = p * t + coe[c][4];
            p = p * t + coe[c][3];
            p = p * t + coe[c][2];
            p = p * t + coe[c][1];
            p = p * t + coe[c][0];
            pos[c] = p;
            float v = 5.0f * coe[c][5];
            v = v * t + 4.0f * coe[c][4];
            v = v * t + 3.0f * coe[c][3];
            v = v * t + 2.0f * coe[c][2];
            v = v * t + 1.0f * coe[c][1];
            vel[c] = v;
        }

        const float gdx = sG[0] - pos[0];
        const float gdy = sG[1] - pos[1];
        const float gdz = sG[2] - pos[2];

        // --- pitch penalty ---
        const float pg = atan2f(gdz, sqrtf(gdx * gdx + gdy * gdy + 1e-6f));
        const float pv = atan2f(vel[2], sqrtf(vel[0] * vel[0] + vel[1] * vel[1] + 1e-6f));
        pen_val = fmaxf(fabsf(pg - pv) - VFOV_C, 0.0f);

        // --- occlusion: 10 LOS samples, trilinear SDF lookups ---
        const float* __restrict__ map = sdf + (long long)sMap * MAP_ELEMS;
        const float mb0 = sMb[0], mb1 = sMb[1], mb2 = sMb[2];

        float occ_sum = 0.0f;
        #pragma unroll
        for (int s = 0; s < NS; s++) {
            const float a  = (float)s * (1.0f / 9.0f);
            const float Px = pos[0] + a * gdx;
            const float Py = pos[1] + a * gdy;
            const float Pz = pos[2] + a * gdz;

            const float gx = (Px - mb0) / 0.2f;
            const float gy = (Py - mb1) / 0.2f;
            const float gz = (Pz - mb2) / 0.2f;

            const bool valid = (gx > 0.5f) && (gx < (float)GDIM - 1.5f)
                            && (gy > 0.5f) && (gy < (float)GDIM - 1.5f)
                            && (gz > 0.5f) && (gz < (float)GDIM - 1.5f);

            float cost = 0.0f;  // invalid -> cost 0 -> relu(0.2-0)=0.2 contribution
            if (valid) {
                const float x0f = fminf(fmaxf(floorf(gx), 0.0f), (float)(GDIM - 2));
                const float y0f = fminf(fmaxf(floorf(gy), 0.0f), (float)(GDIM - 2));
                const float z0f = fminf(fmaxf(floorf(gz), 0.0f), (float)(GDIM - 2));
                const float fx = gx - x0f, fy = gy - y0f, fz = gz - z0f;
                const int ix = (int)x0f, iy = (int)y0f, iz = (int)z0f;
                const int base = iz * (GDIM * GDIM) + iy * GDIM + ix;

                const float c000 = __ldg(map + base);
                const float c001 = __ldg(map + base + 1);
                const float c010 = __ldg(map + base + GDIM);
                const float c011 = __ldg(map + base + GDIM + 1);
                const float c100 = __ldg(map + base + GDIM * GDIM);
                const float c101 = __ldg(map + base + GDIM * GDIM + 1);
                const float c110 = __ldg(map + base + GDIM * GDIM + GDIM);
                const float c111 = __ldg(map + base + GDIM * GDIM + GDIM + 1);

                const float omx = 1.0f - fx, omy = 1.0f - fy;
                const float c0 = (c000 * omx + c001 * fx) * omy
                               + (c010 * omx + c011 * fx) * fy;
                const float c1 = (c100 * omx + c101 * fx) * omy
                               + (c110 * omx + c111 * fx) * fy;
                const float dist = c0 * (1.0f - fz) + c1 * fz;
                cost = expf(-(dist - 0.6f) / 0.3f);
            }
            occ_sum += fmaxf(0.2f - cost, 0.0f);
        }
        occ_val = occ_sum * (1.0f / (float)NS);
    }

    sOcc[tid] = occ_val;
    sPen[tid] = pen_val;
    __syncthreads();

    // reduce the NT time samples of each trajectory
    if (tid < TRAJ) {
        float so = 0.0f, sp = 0.0f;
        #pragma unroll
        for (int k = 0; k < NT; k++) {
            so += sOcc[tid * NT + k];
            sp += sPen[tid * NT + k];
        }
        const float occ_loss   = so * (1.0f / (float)NT);
        const float pitch_loss = sp * (1.0f / (float)NT);
        out[o * TRAJ + tid] = (occ_loss * 4.0f + pitch_loss) * 5.0f;
    }
}

extern "C" void kernel_launch(void* const* d_in, const int* in_sizes, int n_in,
                              void* d_out, int out_size)
{
    const float* Df     = (const float*)d_in[0];
    const float* Dp     = (const float*)d_in[1];
    const float* goal   = (const float*)d_in[2];
    const float* L      = (const float*)d_in[3];
    const float* sdf    = (const float*)d_in[4];
    const float* minb   = (const float*)d_in[5];
    const int*   map_id = (const int*)d_in[6];
    float* out = (float*)d_out;

    const int outer = in_sizes[6];   // number of outer groups (map_id count)

    track_loss_kernel<<<outer, 256>>>(Df, Dp, goal, L, sdf, minb, map_id, out);
}